// round 5
// baseline (speedup 1.0000x reference)
#include <cuda_runtime.h>

#define Bn      128
#define DMODEL  1024
#define DMEM    64
#define NH      16
#define NMEM    4096

typedef unsigned long long u64;

// ---- packed f32x2 helpers (sm_103a) ----
__device__ __forceinline__ u64 pack2(float x, float y) {
    u64 r;
    asm("mov.b64 %0, {%1, %2};" : "=l"(r)
        : "r"(__float_as_uint(x)), "r"(__float_as_uint(y)));
    return r;
}
__device__ __forceinline__ u64 ffma2(u64 a, u64 b, u64 c) {
    u64 d;
    asm("fma.rn.f32x2 %0, %1, %2, %3;" : "=l"(d) : "l"(a), "l"(b), "l"(c));
    return d;
}

// ---- scratch (no allocation allowed; __device__ globals) ----
__device__ float g_qa[Bn * DMODEL];          // relu(query @ Wq^T + bq)
__device__ float g_mat[Bn * DMEM * DMEM];    // per-batch 64x64 kernel matrix
__device__ float g_norm[Bn * DMEM];          // per-batch normalizer
__device__ float g_attn[Bn * DMODEL];        // attention output, flattened

// ============================================================
// Stage 1: matrix[b] = relu(mem[b]+addr)^T @ mem[b],  norm[b] = sum_n k
// One block per batch. 256 threads; thread (tx,ty) owns the 4x4 tile
// (d = 4*ty..+3, e = 4*tx..+3) of the 64x64 accumulator, kept as f32x2
// pairs along e. Double-buffered smem chunks of CN=32 memory rows.
// ============================================================
#define CN 32
#define NCHUNK (NMEM / CN)

__global__ __launch_bounds__(256) void stage1_kernel(
    const float* __restrict__ mem, const float* __restrict__ addr)
{
    __shared__ float s_m[2][CN][DMEM];   // raw memories chunk
    __shared__ float s_k[2][CN][DMEM];   // relu(mem+addr) chunk
    __shared__ float s_np[16][DMEM];     // normalizer partials

    const int b   = blockIdx.x;
    const int tid = threadIdx.x;
    const int tx  = tid & 15;
    const int ty  = tid >> 4;
    const int lc  = tx * 4;              // load column (same every chunk)

    const float* mb = mem + (size_t)b * NMEM * DMEM;

    u64 acc[4][2];
#pragma unroll
    for (int i = 0; i < 4; i++) { acc[i][0] = 0ull; acc[i][1] = 0ull; }
    float4 nacc = make_float4(0.f, 0.f, 0.f, 0.f);

    float4 rm[2], ra[2];

    auto ldg_chunk = [&](int ch) {
        const float* pm = mb   + ((size_t)ch * CN + ty) * DMEM + lc;
        const float* pa = addr + ((size_t)ch * CN + ty) * DMEM + lc;
        rm[0] = *(const float4*)pm;
        rm[1] = *(const float4*)(pm + 16 * DMEM);
        ra[0] = *(const float4*)pa;
        ra[1] = *(const float4*)(pa + 16 * DMEM);
    };
    auto sts_chunk = [&](int buf) {
#pragma unroll
        for (int h = 0; h < 2; h++) {
            int r = ty + 16 * h;
            float4 m4 = rm[h], a4 = ra[h], k4;
            k4.x = fmaxf(m4.x + a4.x, 0.f);
            k4.y = fmaxf(m4.y + a4.y, 0.f);
            k4.z = fmaxf(m4.z + a4.z, 0.f);
            k4.w = fmaxf(m4.w + a4.w, 0.f);
            *(float4*)&s_m[buf][r][lc] = m4;
            *(float4*)&s_k[buf][r][lc] = k4;
            nacc.x += k4.x; nacc.y += k4.y; nacc.z += k4.z; nacc.w += k4.w;
        }
    };

    ldg_chunk(0);
    sts_chunk(0);
    __syncthreads();

    for (int ch = 0; ch < NCHUNK; ch++) {
        const int cur = ch & 1;
        if (ch + 1 < NCHUNK) ldg_chunk(ch + 1);

#pragma unroll 8
        for (int n = 0; n < CN; n++) {
            float4     kv = *(const float4*)&s_k[cur][n][ty * 4];
            ulonglong2 mv = *(const ulonglong2*)&s_m[cur][n][tx * 4];
            u64 kd;
            kd = pack2(kv.x, kv.x);
            acc[0][0] = ffma2(kd, mv.x, acc[0][0]);
            acc[0][1] = ffma2(kd, mv.y, acc[0][1]);
            kd = pack2(kv.y, kv.y);
            acc[1][0] = ffma2(kd, mv.x, acc[1][0]);
            acc[1][1] = ffma2(kd, mv.y, acc[1][1]);
            kd = pack2(kv.z, kv.z);
            acc[2][0] = ffma2(kd, mv.x, acc[2][0]);
            acc[2][1] = ffma2(kd, mv.y, acc[2][1]);
            kd = pack2(kv.w, kv.w);
            acc[3][0] = ffma2(kd, mv.x, acc[3][0]);
            acc[3][1] = ffma2(kd, mv.y, acc[3][1]);
        }
        __syncthreads();
        if (ch + 1 < NCHUNK) {
            sts_chunk((ch + 1) & 1);
            __syncthreads();
        }
    }

    // write matrix tile (pairs are (e, e+1): low word = first element)
    float* om = g_mat + (size_t)b * DMEM * DMEM + (ty * 4) * DMEM + tx * 4;
#pragma unroll
    for (int i = 0; i < 4; i++) {
        ulonglong2 v;
        v.x = acc[i][0];
        v.y = acc[i][1];
        *(ulonglong2*)(om + i * DMEM) = v;
    }

    // normalizer: per-thread partial covers columns lc..lc+3 (fixed all run)
    *(float4*)&s_np[ty][lc] = nacc;
    __syncthreads();
    if (tid < DMEM) {
        float s = 0.f;
#pragma unroll
        for (int g = 0; g < 16; g++) s += s_np[g][tid];
        g_norm[b * DMEM + tid] = s;
    }
}

// ============================================================
// NT GEMM: C[128,1024] = A[128,1024] @ W[1024,1024]^T + bias
// mode 0: A = A_ext (query), C = g_qa, fused relu
// mode 1: A = g_attn,        C = C_ext, no relu
// 32x32 block tiles (grid 32x4 = 128 blocks), 2x2 per thread.
// ============================================================
__global__ __launch_bounds__(256) void gemm_nt(
    const float* __restrict__ A_ext, const float* __restrict__ W,
    const float* __restrict__ bias, float* __restrict__ C_ext, int mode)
{
    __shared__ float As[32][33];
    __shared__ float Ws[32][33];

    const float* A = (mode == 0) ? A_ext : g_attn;
    float*       C = (mode == 0) ? g_qa : C_ext;

    const int tid = threadIdx.x;
    const int tx  = tid & 15;
    const int ty  = tid >> 4;
    const int bm  = blockIdx.y * 32;
    const int bn  = blockIdx.x * 32;
    const int lr  = tid >> 3;            // 0..31
    const int lc  = (tid & 7) * 4;       // 0..28

    float acc00 = 0.f, acc01 = 0.f, acc10 = 0.f, acc11 = 0.f;

    for (int k0 = 0; k0 < DMODEL; k0 += 32) {
        float4 a4 = *(const float4*)(A + (size_t)(bm + lr) * DMODEL + k0 + lc);
        float4 w4 = *(const float4*)(W + (size_t)(bn + lr) * DMODEL + k0 + lc);
        __syncthreads();   // previous iteration's reads complete
        As[lr][lc + 0] = a4.x; As[lr][lc + 1] = a4.y;
        As[lr][lc + 2] = a4.z; As[lr][lc + 3] = a4.w;
        Ws[lr][lc + 0] = w4.x; Ws[lr][lc + 1] = w4.y;
        Ws[lr][lc + 2] = w4.z; Ws[lr][lc + 3] = w4.w;
        __syncthreads();
#pragma unroll
        for (int k = 0; k < 32; k++) {
            float a0 = As[2 * ty + 0][k];
            float a1 = As[2 * ty + 1][k];
            float w0 = Ws[2 * tx + 0][k];
            float w1 = Ws[2 * tx + 1][k];
            acc00 += a0 * w0; acc01 += a0 * w1;
            acc10 += a1 * w0; acc11 += a1 * w1;
        }
    }

    float r[2][2] = {{acc00, acc01}, {acc10, acc11}};
#pragma unroll
    for (int i = 0; i < 2; i++) {
#pragma unroll
        for (int j = 0; j < 2; j++) {
            int m = bm + 2 * ty + i;
            int n = bn + 2 * tx + j;
            float v = r[i][j] + bias[n];
            if (mode == 0) v = fmaxf(v, 0.f);
            C[(size_t)m * DMODEL + n] = v;
        }
    }
}

// ============================================================
// Stage 2 read: attn[b,h,:] = (qa[b,h,:] @ matrix[b]) / (qa.norm + 1e-5)
// grid (H, B), 64 threads; thread = output column e (also index d for
// the denominator reduce). matrix[b] (16 KB) is L2-resident across heads.
// ============================================================
__global__ __launch_bounds__(64) void attn_read_kernel()
{
    __shared__ float s_q[DMEM];
    __shared__ float s_d[2];

    const int h = blockIdx.x;
    const int b = blockIdx.y;
    const int e = threadIdx.x;

    float qv = g_qa[(size_t)b * DMODEL + h * DMEM + e];   // already relu'd
    s_q[e] = qv;

    // denominator: sum_d qa[d] * norm[d]
    float p = qv * g_norm[b * DMEM + e];
#pragma unroll
    for (int o = 16; o > 0; o >>= 1) p += __shfl_down_sync(0xffffffffu, p, o);
    if ((e & 31) == 0) s_d[e >> 5] = p;
    __syncthreads();
    float denom = s_d[0] + s_d[1] + 1e-5f;

    const float* mrow = g_mat + (size_t)b * DMEM * DMEM;
    float acc = 0.f;
#pragma unroll 8
    for (int d = 0; d < DMEM; d++) acc += s_q[d] * mrow[d * DMEM + e];

    g_attn[(size_t)b * DMODEL + h * DMEM + e] = acc / denom;
}

// ============================================================
extern "C" void kernel_launch(void* const* d_in, const int* in_sizes, int n_in,
                              void* d_out, int out_size)
{
    (void)in_sizes; (void)n_in; (void)out_size;
    const float* query     = (const float*)d_in[0];
    const float* addresses = (const float*)d_in[1];
    const float* memories  = (const float*)d_in[2];
    const float* Wq        = (const float*)d_in[3];
    const float* bq        = (const float*)d_in[4];
    const float* Wm        = (const float*)d_in[5];
    const float* bm        = (const float*)d_in[6];
    float* out = (float*)d_out;

    // qa = relu(query @ Wq^T + bq)  -> g_qa
    gemm_nt<<<dim3(32, 4), 256>>>(query, Wq, bq, nullptr, 0);
    // matrix / normalizer            -> g_mat, g_norm
    stage1_kernel<<<Bn, 256>>>(memories, addresses);
    // attn                           -> g_attn
    attn_read_kernel<<<dim3(NH, Bn), 64>>>();
    // out = attn @ Wm^T + bm
    gemm_nt<<<dim3(32, 4), 256>>>(nullptr, Wm, bm, out, 1);
}